// round 5
// baseline (speedup 1.0000x reference)
#include <cuda_runtime.h>
#include <cstdint>

// Elementwise: out = (x+2) + 3x - (x-1)*(x/2)  ==  -0.5*x^2 + 4.5*x + 2
// N = 8192*16384 = 134217728 -> n_vec = 33554432 float4.
// Flat launch, each thread handles 4 float4s split across four quarters:
//   i, i+q, i+2q, i+3q  with q = n_vec/4 = 8388608 = 32768 blocks * 256.
// Exact coverage -> no guard, no tail, no loop.

#define THREADS 256

__global__ __launch_bounds__(THREADS) void fused_elem_kernel(
    const float4* __restrict__ x, float4* __restrict__ out, int quarter)
{
    const int i0 = blockIdx.x * THREADS + threadIdx.x;
    const int i1 = i0 + quarter;
    const int i2 = i1 + quarter;
    const int i3 = i2 + quarter;

    // Front-batch four independent LDG.128s (per-warp MLP=4, zero loop state)
    float4 a = __ldcs(&x[i0]);
    float4 b = __ldcs(&x[i1]);
    float4 c = __ldcs(&x[i2]);
    float4 d = __ldcs(&x[i3]);

    float4 r;
    r.x = fmaf(a.x, fmaf(a.x, -0.5f, 4.5f), 2.0f);
    r.y = fmaf(a.y, fmaf(a.y, -0.5f, 4.5f), 2.0f);
    r.z = fmaf(a.z, fmaf(a.z, -0.5f, 4.5f), 2.0f);
    r.w = fmaf(a.w, fmaf(a.w, -0.5f, 4.5f), 2.0f);
    __stcs(&out[i0], r);

    r.x = fmaf(b.x, fmaf(b.x, -0.5f, 4.5f), 2.0f);
    r.y = fmaf(b.y, fmaf(b.y, -0.5f, 4.5f), 2.0f);
    r.z = fmaf(b.z, fmaf(b.z, -0.5f, 4.5f), 2.0f);
    r.w = fmaf(b.w, fmaf(b.w, -0.5f, 4.5f), 2.0f);
    __stcs(&out[i1], r);

    r.x = fmaf(c.x, fmaf(c.x, -0.5f, 4.5f), 2.0f);
    r.y = fmaf(c.y, fmaf(c.y, -0.5f, 4.5f), 2.0f);
    r.z = fmaf(c.z, fmaf(c.z, -0.5f, 4.5f), 2.0f);
    r.w = fmaf(c.w, fmaf(c.w, -0.5f, 4.5f), 2.0f);
    __stcs(&out[i2], r);

    r.x = fmaf(d.x, fmaf(d.x, -0.5f, 4.5f), 2.0f);
    r.y = fmaf(d.y, fmaf(d.y, -0.5f, 4.5f), 2.0f);
    r.z = fmaf(d.z, fmaf(d.z, -0.5f, 4.5f), 2.0f);
    r.w = fmaf(d.w, fmaf(d.w, -0.5f, 4.5f), 2.0f);
    __stcs(&out[i3], r);
}

extern "C" void kernel_launch(void* const* d_in, const int* in_sizes, int n_in,
                              void* d_out, int out_size) {
    const float* x = (const float*)d_in[0];
    float* out = (float*)d_out;
    int n = in_sizes[0];        // 134217728
    int n_vec = n >> 2;         // 33554432
    int quarter = n_vec >> 2;   // 8388608

    int blocks = quarter / THREADS;   // 32768, exact
    fused_elem_kernel<<<blocks, THREADS>>>((const float4*)x, (float4*)out, quarter);
}

// round 6
// speedup vs baseline: 1.0123x; 1.0123x over previous
#include <cuda_runtime.h>
#include <cstdint>

// Elementwise: out = (x+2) + 3x - (x-1)*(x/2)  ==  -0.5*x^2 + 4.5*x + 2
// N = 8192*16384 = 134217728 -> n_vec = 33554432 float4.
// Flat launch, MLP=2: thread handles vectors i and i + n_vec/2.
// half = 16777216 = 32768 blocks * 512 threads exactly -> no guard, no tail.

#define THREADS 512

__global__ __launch_bounds__(THREADS) void fused_elem_kernel(
    const float4* __restrict__ x, float4* __restrict__ out, int half)
{
    const int i = blockIdx.x * THREADS + threadIdx.x;
    const int j = i + half;

    // Front-batch both independent loads (MLP=2, zero loop state)
    float4 a = __ldcs(&x[i]);
    float4 b = __ldcs(&x[j]);

    float4 ra, rb;
    ra.x = fmaf(a.x, fmaf(a.x, -0.5f, 4.5f), 2.0f);
    ra.y = fmaf(a.y, fmaf(a.y, -0.5f, 4.5f), 2.0f);
    ra.z = fmaf(a.z, fmaf(a.z, -0.5f, 4.5f), 2.0f);
    ra.w = fmaf(a.w, fmaf(a.w, -0.5f, 4.5f), 2.0f);
    __stcs(&out[i], ra);

    rb.x = fmaf(b.x, fmaf(b.x, -0.5f, 4.5f), 2.0f);
    rb.y = fmaf(b.y, fmaf(b.y, -0.5f, 4.5f), 2.0f);
    rb.z = fmaf(b.z, fmaf(b.z, -0.5f, 4.5f), 2.0f);
    rb.w = fmaf(b.w, fmaf(b.w, -0.5f, 4.5f), 2.0f);
    __stcs(&out[j], rb);
}

extern "C" void kernel_launch(void* const* d_in, const int* in_sizes, int n_in,
                              void* d_out, int out_size) {
    const float* x = (const float*)d_in[0];
    float* out = (float*)d_out;
    int n = in_sizes[0];       // 134217728
    int n_vec = n >> 2;        // 33554432
    int half = n_vec >> 1;     // 16777216

    int blocks = half / THREADS;   // 32768, exact
    fused_elem_kernel<<<blocks, THREADS>>>((const float4*)x, (float4*)out, half);
}